// round 16
// baseline (speedup 1.0000x reference)
#include <cuda_runtime.h>
#include <cuda_fp16.h>
#include <cstdint>
#define DI __device__ __forceinline__

constexpr int Bn=16, Sn=1024, WA=768, WB=512;
__device__ __align__(128) unsigned short g_A[Bn*Sn*WA];   // [c|s|d], d=c-s
__device__ __align__(128) unsigned short g_B[Bn*Sn*WB];   // [c|s]

DI unsigned short f2h(float x){ __half h=__float2half_rn(x); return *(unsigned short*)&h; }

// kernel 1: amplitudes (fp16)
__global__ void iqp_amp_kernel(const float* __restrict__ Q, const float* __restrict__ K){
  const int isK=blockIdx.y;
  const float* X = isK?K:Q;
  const int t0 = blockIdx.x*16;
  __shared__ float xs[16][8];
  const int tid=threadIdx.x;
  if(tid<128) xs[tid>>3][tid&7]=X[t0*8+tid];
  __syncthreads();
  const int z=tid;
  unsigned short* G = isK? g_B : g_A;
  const int Wl = isK? WB : WA;
#pragma unroll 4
  for(int t=0;t<16;++t){
    float sq=0.f,L=0.f;
#pragma unroll
    for(int i=0;i<8;++i){ float xi=xs[t][i]; sq+=xi*xi; L+=((z>>i)&1)?-xi:xi; }
    float ph=-0.5f*L-0.25f*(L*L-sq), s,c; __sincosf(ph,&s,&c);
    size_t base=(size_t)(t0+t)*Wl;
    G[base+z]=f2h(c); G[base+256+z]=f2h(s);
    if(!isK) G[base+512+z]=f2h(c-s);
  }
}

// kernel 2: i-tile 64, 2 CTAs/SM, z-chunks of 64, Karatsuba with precomputed A d-plane.
// passes: X += aC*bC (f32) ; Y += aS*bS (f16) ; Z += aD*(bC+bS) (f16). re=X+Y, im=Z-X+Y.
constexpr int STG=57344;       // A c,s,d [64x64]x3=24KB ; B c,s [128x64]x2=32KB
constexpr int SM_TOTAL=114688; // 2 stages; post-loop: RED[0:8192) CS[8192:9216) SV[9216)

DI uint32_t swz(int r,int c){ return (uint32_t)(r*128 + ((c^(r&7))<<4)); }
DI void cp16(uint32_t d,const void* s){ asm volatile("cp.async.cg.shared.global [%0],[%1],16;\n"::"r"(d),"l"(s):"memory"); }
DI void cpc(){ asm volatile("cp.async.commit_group;\n":::"memory"); }
DI void ldsm_x4(uint32_t* r,uint32_t a){
  asm volatile("ldmatrix.sync.aligned.m8n8.x4.shared.b16 {%0,%1,%2,%3},[%4];\n"
    :"=r"(r[0]),"=r"(r[1]),"=r"(r[2]),"=r"(r[3]):"r"(a));
}
DI void mma16816(float* c,const uint32_t* a,uint32_t b0,uint32_t b1){
  asm volatile("mma.sync.aligned.m16n8k16.row.col.f32.f16.f16.f32 {%0,%1,%2,%3},{%4,%5,%6,%7},{%8,%9},{%0,%1,%2,%3};\n"
    :"+f"(c[0]),"+f"(c[1]),"+f"(c[2]),"+f"(c[3])
    :"r"(a[0]),"r"(a[1]),"r"(a[2]),"r"(a[3]),"r"(b0),"r"(b1));
}
DI void mma16816_z(float* d,const uint32_t* a,uint32_t b0,uint32_t b1){
  asm volatile("mma.sync.aligned.m16n8k16.row.col.f32.f16.f16.f32 {%0,%1,%2,%3},{%4,%5,%6,%7},{%8,%9},{%10,%10,%10,%10};\n"
    :"=f"(d[0]),"=f"(d[1]),"=f"(d[2]),"=f"(d[3])
    :"r"(a[0]),"r"(a[1]),"r"(a[2]),"r"(a[3]),"r"(b0),"r"(b1),"f"(0.0f));
}
DI void mma16816h(uint32_t* c,const uint32_t* a,uint32_t b0,uint32_t b1){
  asm volatile("mma.sync.aligned.m16n8k16.row.col.f16.f16.f16.f16 {%0,%1},{%2,%3,%4,%5},{%6,%7},{%0,%1};\n"
    :"+r"(c[0]),"+r"(c[1])
    :"r"(a[0]),"r"(a[1]),"r"(a[2]),"r"(a[3]),"r"(b0),"r"(b1));
}
DI void mma16816h_z(uint32_t* d,const uint32_t* a,uint32_t b0,uint32_t b1){
  asm volatile("mma.sync.aligned.m16n8k16.row.col.f16.f16.f16.f16 {%0,%1},{%2,%3,%4,%5},{%6,%7},{%8,%8};\n"
    :"=r"(d[0]),"=r"(d[1])
    :"r"(a[0]),"r"(a[1]),"r"(a[2]),"r"(a[3]),"r"(b0),"r"(b1),"r"(0u));
}
DI uint32_t pack2(float lo,float hi){ uint32_t r; asm("cvt.rn.f16x2.f32 %0,%1,%2;\n":"=r"(r):"f"(hi),"f"(lo)); return r; }
DI uint32_t hadd2(uint32_t a,uint32_t b){ uint32_t r; asm("add.f16x2 %0,%1,%2;\n":"=r"(r):"r"(a),"r"(b)); return r; }
DI void unp(uint32_t r,float& lo,float& hi){ __half2 h=*reinterpret_cast<__half2*>(&r); lo=__low2float(h); hi=__high2float(h); }

__global__ __launch_bounds__(256,2)
void qattn_kernel(const float* __restrict__ V, float* __restrict__ Out){
  extern __shared__ char smem[];
  const uint32_t sb=(uint32_t)__cvta_generic_to_shared(smem);
  const int b=blockIdx.y, it=blockIdx.x, tid=threadIdx.x;
  const int lane=tid&31, warp=tid>>5;
  const int wm=warp>>2, wn=warp&3;   // 2M x 4N warps, 32x32 tiles over [64 x 128]

  const unsigned short* gAi = g_A + (size_t)(b*Sn+it*64)*WA;
  const unsigned short* gBb = g_B + (size_t)b*Sn*WB;

  auto loadChunk=[&](int jt,int zc,int st){
    uint32_t base=sb+(uint32_t)(st*STG);
#pragma unroll
    for(int p=0;p<3;++p){               // A planes c,s,d: [64x64] each
      const unsigned short* src=gAi + p*256 + zc*64;
      uint32_t dst=base+p*8192;
#pragma unroll
      for(int m=0;m<2;++m){ int ch=tid+m*256, r=ch>>3, cx=ch&7;
        cp16(dst+swz(r,cx), src+(size_t)r*WA+cx*8); }
    }
#pragma unroll
    for(int p=0;p<2;++p){               // B planes c,s: [128x64] each
      const unsigned short* src=gBb + (size_t)jt*128*WB + p*256 + zc*64;
      uint32_t dst=base+24576+p*16384;
#pragma unroll
      for(int m=0;m<4;++m){ int ch=tid+m*256, r=ch>>3, cx=ch&7;
        cp16(dst+swz(r,cx), src+(size_t)r*WB+cx*8); }
    }
    cpc();
  };
  loadChunk(0,0,0);

  const float* gV = V + (size_t)b*Sn*8;

  float accX[2][4][4];                   // m1 (f32)
  uint32_t accY[2][4][2], accZ[2][4][2]; // m2, m3 (f16x2)
  float accO[2][4];
#pragma unroll
  for(int m=0;m<2;++m)
#pragma unroll
    for(int x=0;x<4;++x){ accO[m][x]=0.f; }

  const int lr=lane&15, lch=lane>>4;
  const int brow=(lane&7)+((lane>>4)<<3), bco=(lane>>3)&1;
  const int ve=lane>>2, vj=2*(lane&3);
  const float sc=2.0f/65536.0f;

  for(int jt=0;jt<8;++jt){
#pragma unroll
    for(int zc=0;zc<4;++zc){            // zc compile-time
      asm volatile("cp.async.wait_group 0;\n":::"memory");
      __syncthreads();
      if(jt<7||zc<3){                    // prefetch next chunk into other stage
        int nj=(zc==3)?jt+1:jt, nz=(zc==3)?0:zc+1;
        loadChunk(nj,nz,(zc+1)&1);
      }
      uint32_t vf[2][2];
      if(zc==3){                         // hoist V frag LDGs over the last chunk
#pragma unroll
        for(int q=0;q<2;++q){
          int j0=jt*128+wn*32+q*16+vj;
          float v0=gV[j0*8+ve],     v1=gV[(j0+1)*8+ve];
          float v2=gV[(j0+8)*8+ve], v3=gV[(j0+9)*8+ve];
          vf[q][0]=pack2(v0,v1); vf[q][1]=pack2(v2,v3);
        }
      }
      const uint32_t base=sb+(uint32_t)((zc&1)*STG);

#pragma unroll
      for(int k16=0;k16<4;++k16){
        uint32_t aC[2][4], aS[2][4], aD[2][4], bC[2][4], bS[2][4];
#pragma unroll
        for(int m=0;m<2;++m){
          ldsm_x4(aC[m], base+        swz(wm*32+m*16+lr, k16*2+lch));
          ldsm_x4(aS[m], base+8192 +  swz(wm*32+m*16+lr, k16*2+lch));
        }
#pragma unroll
        for(int h=0;h<2;++h){
          ldsm_x4(bC[h], base+24576 + swz(wn*32+h*16+brow, k16*2+bco));
          ldsm_x4(bS[h], base+40960 + swz(wn*32+h*16+brow, k16*2+bco));
        }
        // pass 1: X += aC*bC  (m1, f32)   -- aC dies here
#pragma unroll
        for(int m=0;m<2;++m)
#pragma unroll
          for(int nf=0;nf<4;++nf){
            uint32_t b0=bC[nf>>1][(nf&1)*2], b1=bC[nf>>1][(nf&1)*2+1];
            if(zc==0&&k16==0) mma16816_z(accX[m][nf], aC[m], b0, b1);
            else              mma16816  (accX[m][nf], aC[m], b0, b1);
          }
        // load precomputed d-plane (reuses aC's registers)
#pragma unroll
        for(int m=0;m<2;++m)
          ldsm_x4(aD[m], base+16384 + swz(wm*32+m*16+lr, k16*2+lch));
        // pass 2: Y += aS*bS  (m2, f16 acc) -- aS dies here
#pragma unroll
        for(int m=0;m<2;++m)
#pragma unroll
          for(int nf=0;nf<4;++nf){
            uint32_t b0=bS[nf>>1][(nf&1)*2], b1=bS[nf>>1][(nf&1)*2+1];
            if(zc==0&&k16==0) mma16816h_z(accY[m][nf], aS[m], b0, b1);
            else              mma16816h  (accY[m][nf], aS[m], b0, b1);
          }
        // e = bC + bS (overwrite bC)
#pragma unroll
        for(int h=0;h<2;++h)
#pragma unroll
          for(int i=0;i<4;++i) bC[h][i]=hadd2(bC[h][i],bS[h][i]);
        // pass 3: Z += d*e  (m3, f16 acc)
#pragma unroll
        for(int m=0;m<2;++m)
#pragma unroll
          for(int nf=0;nf<4;++nf){
            uint32_t b0=bC[nf>>1][(nf&1)*2], b1=bC[nf>>1][(nf&1)*2+1];
            if(zc==0&&k16==0) mma16816h_z(accZ[m][nf], aD[m], b0, b1);
            else              mma16816h  (accZ[m][nf], aD[m], b0, b1);
          }
      }

      if(zc==3){   // re=X+Y, im=Z-X+Y ; P=2*fid -> f16 A-frags -> P@V
#pragma unroll
        for(int m=0;m<2;++m)
#pragma unroll
          for(int q=0;q<2;++q){
            const int n0=2*q, n1=2*q+1;
            float y0[4],z0[4],y1[4],z1[4];
            unp(accY[m][n0][0],y0[0],y0[1]); unp(accY[m][n0][1],y0[2],y0[3]);
            unp(accZ[m][n0][0],z0[0],z0[1]); unp(accZ[m][n0][1],z0[2],z0[3]);
            unp(accY[m][n1][0],y1[0],y1[1]); unp(accY[m][n1][1],y1[2],y1[3]);
            unp(accZ[m][n1][0],z1[0],z1[1]); unp(accZ[m][n1][1],z1[2],z1[3]);
            float p[8];
#pragma unroll
            for(int x=0;x<4;++x){
              float u0=accX[m][n0][x]+y0[x];
              float v0=z0[x]-accX[m][n0][x]+y0[x];
              float u1=accX[m][n1][x]+y1[x];
              float v1=z1[x]-accX[m][n1][x]+y1[x];
              p[x]  =(u0*u0+v0*v0)*sc;
              p[4+x]=(u1*u1+v1*v1)*sc;
            }
            uint32_t pa[4]={pack2(p[0],p[1]),pack2(p[2],p[3]),pack2(p[4],p[5]),pack2(p[6],p[7])};
            mma16816(accO[m], pa, vf[q][0], vf[q][1]);
          }
        // no re-zeroing: next jt's first mma uses the zero-C forms
      }
    }
  }

  __syncthreads();
  // phase 1: write O partials (RED @ ring[0..8192)) + colsum partials (CS @ [8192..9216))
  {
    float* red=(float*)(smem)+wn*512;
    const int g=lane>>2, e0=(lane&3)*2;
#pragma unroll
    for(int m=0;m<2;++m){
      int r0=wm*32+m*16+g;
      red[r0*8+e0]=accO[m][0];     red[r0*8+e0+1]=accO[m][1];
      red[(r0+8)*8+e0]=accO[m][2]; red[(r0+8)*8+e0+1]=accO[m][3];
    }
    int e=tid&7, jg=tid>>3; float part=0.f;
#pragma unroll
    for(int k=0;k<32;++k) part+=gV[(jg+k*32)*8+e];
    *(float*)(smem+8192+(jg*8+e)*4)=part;
  }
  __syncthreads();
  if(tid<8){ float s=0.f; for(int g=0;g<32;++g) s+=*(float*)(smem+8192+(g*8+tid)*4);
             *(float*)(smem+9216+tid*4)=s; }
  __syncthreads();
  const float* redall=(const float*)(smem);
  size_t ob=(size_t)(b*Sn+it*64)*8;
#pragma unroll
  for(int rep=0;rep<2;++rep){
    int idx=tid+rep*256, e=idx&7;
    float v=redall[idx]+redall[512+idx]+redall[1024+idx]+redall[1536+idx]
           -*(const float*)(smem+9216+e*4);
    Out[ob+idx]=v;
  }
}

extern "C" void kernel_launch(void* const* d_in,const int* in_sizes,int n_in,void* d_out,int out_size){
  (void)in_sizes;(void)n_in;(void)out_size;
  const float* Q=(const float*)d_in[0];
  const float* K=(const float*)d_in[1];
  const float* V=(const float*)d_in[2];
  float* Out=(float*)d_out;
  dim3 g1(Bn*Sn/16,2);
  iqp_amp_kernel<<<g1,256>>>(Q,K);
  cudaFuncSetAttribute(qattn_kernel,cudaFuncAttributeMaxDynamicSharedMemorySize,SM_TOTAL);
  dim3 g2(16,Bn);
  qattn_kernel<<<g2,256,SM_TOTAL>>>(V,Out);
}

// round 17
// speedup vs baseline: 1.1481x; 1.1481x over previous
#include <cuda_runtime.h>
#include <cuda_fp16.h>
#include <cstdint>
#define DI __device__ __forceinline__

constexpr int Bn=16, Sn=1024, W=512;
__device__ __align__(128) unsigned short g_A[Bn*Sn*W];   // [c|s] scaled by 1/16
__device__ __align__(128) unsigned short g_B[Bn*Sn*W];   // [c|s] scaled by 1/16

DI unsigned short f2h(float x){ __half h=__float2half_rn(x); return *(unsigned short*)&h; }

// kernel 1: amplitudes (fp16, scaled 1/16)
__global__ void iqp_amp_kernel(const float* __restrict__ Q, const float* __restrict__ K){
  const int isK=blockIdx.y;
  const float* X = isK?K:Q;
  const int t0 = blockIdx.x*16;
  __shared__ float xs[16][8];
  const int tid=threadIdx.x;
  if(tid<128) xs[tid>>3][tid&7]=X[t0*8+tid];
  __syncthreads();
  const int z=tid;
  unsigned short* G = isK? g_B : g_A;
#pragma unroll 4
  for(int t=0;t<16;++t){
    float sq=0.f,L=0.f;
#pragma unroll
    for(int i=0;i<8;++i){ float xi=xs[t][i]; sq+=xi*xi; L+=((z>>i)&1)?-xi:xi; }
    float ph=-0.5f*L-0.25f*(L*L-sq), s,c; __sincosf(ph,&s,&c);
    size_t base=(size_t)(t0+t)*W;
    G[base+z]=f2h(c*0.0625f); G[base+256+z]=f2h(s*0.0625f);
  }
}

// kernel 2: i-tile 64, 2 CTAs/SM, z-chunks of 64, fragment-Karatsuba, ALL-f16 accs.
// X=m1, Y=m2, Z=m3 (all f16x2, scaled by 1/256). re~X+Y, im~Z-X+Y. P=2(re^2+im^2).
constexpr int STG=49152;       // A c,s [64x64]x2=16KB ; B c,s [128x64]x2=32KB
constexpr int SM_RING=0;       // 2 stages = 98304
constexpr int SM_CS=98304;     // [32][8] f32
constexpr int SM_SV=99328;     // [8] f32
constexpr int SM_RED=0;        // reuse ring after loop
constexpr int SM_TOTAL=99360;

DI uint32_t swz(int r,int c){ return (uint32_t)(r*128 + ((c^(r&7))<<4)); }
DI void cp16(uint32_t d,const void* s){ asm volatile("cp.async.cg.shared.global [%0],[%1],16;\n"::"r"(d),"l"(s):"memory"); }
DI void cpc(){ asm volatile("cp.async.commit_group;\n":::"memory"); }
DI void ldsm_x4(uint32_t* r,uint32_t a){
  asm volatile("ldmatrix.sync.aligned.m8n8.x4.shared.b16 {%0,%1,%2,%3},[%4];\n"
    :"=r"(r[0]),"=r"(r[1]),"=r"(r[2]),"=r"(r[3]):"r"(a));
}
DI void mma16816(float* c,const uint32_t* a,uint32_t b0,uint32_t b1){
  asm volatile("mma.sync.aligned.m16n8k16.row.col.f32.f16.f16.f32 {%0,%1,%2,%3},{%4,%5,%6,%7},{%8,%9},{%0,%1,%2,%3};\n"
    :"+f"(c[0]),"+f"(c[1]),"+f"(c[2]),"+f"(c[3])
    :"r"(a[0]),"r"(a[1]),"r"(a[2]),"r"(a[3]),"r"(b0),"r"(b1));
}
DI void mma16816h(uint32_t* c,const uint32_t* a,uint32_t b0,uint32_t b1){
  asm volatile("mma.sync.aligned.m16n8k16.row.col.f16.f16.f16.f16 {%0,%1},{%2,%3,%4,%5},{%6,%7},{%0,%1};\n"
    :"+r"(c[0]),"+r"(c[1])
    :"r"(a[0]),"r"(a[1]),"r"(a[2]),"r"(a[3]),"r"(b0),"r"(b1));
}
DI void mma16816h_z(uint32_t* d,const uint32_t* a,uint32_t b0,uint32_t b1){
  asm volatile("mma.sync.aligned.m16n8k16.row.col.f16.f16.f16.f16 {%0,%1},{%2,%3,%4,%5},{%6,%7},{%8,%8};\n"
    :"=r"(d[0]),"=r"(d[1])
    :"r"(a[0]),"r"(a[1]),"r"(a[2]),"r"(a[3]),"r"(b0),"r"(b1),"r"(0u));
}
DI uint32_t pack2(float lo,float hi){ uint32_t r; asm("cvt.rn.f16x2.f32 %0,%1,%2;\n":"=r"(r):"f"(hi),"f"(lo)); return r; }
DI uint32_t hsub2(uint32_t a,uint32_t b){ uint32_t r; asm("sub.f16x2 %0,%1,%2;\n":"=r"(r):"r"(a),"r"(b)); return r; }
DI uint32_t hadd2(uint32_t a,uint32_t b){ uint32_t r; asm("add.f16x2 %0,%1,%2;\n":"=r"(r):"r"(a),"r"(b)); return r; }
DI uint32_t hmul2(uint32_t a,uint32_t b){ uint32_t r; asm("mul.f16x2 %0,%1,%2;\n":"=r"(r):"r"(a),"r"(b)); return r; }
DI uint32_t hfma2(uint32_t a,uint32_t b,uint32_t c){ uint32_t r; asm("fma.rn.f16x2 %0,%1,%2,%3;\n":"=r"(r):"r"(a),"r"(b),"r"(c)); return r; }

__global__ __launch_bounds__(256,2)
void qattn_kernel(const float* __restrict__ V, float* __restrict__ Out){
  extern __shared__ char smem[];
  const uint32_t sb=(uint32_t)__cvta_generic_to_shared(smem);
  const int b=blockIdx.y, it=blockIdx.x, tid=threadIdx.x;
  const int lane=tid&31, warp=tid>>5;
  const int wm=warp>>2, wn=warp&3;   // 2M x 4N warps, 32x32 tiles over [64 x 128]

  const unsigned short* gAi = g_A + (size_t)(b*Sn+it*64)*W;
  const unsigned short* gBb = g_B + (size_t)b*Sn*W;

  auto loadChunk=[&](int jt,int zc,int st){
    uint32_t base=sb+SM_RING+(uint32_t)(st*STG);
#pragma unroll
    for(int p=0;p<2;++p){               // A planes c,s: [64x64] each
      const unsigned short* src=gAi + p*256 + zc*64;
      uint32_t dst=base+p*8192;
#pragma unroll
      for(int m=0;m<2;++m){ int ch=tid+m*256, r=ch>>3, cx=ch&7;
        cp16(dst+swz(r,cx), src+(size_t)r*W+cx*8); }
    }
#pragma unroll
    for(int p=0;p<2;++p){               // B planes c,s: [128x64] each
      const unsigned short* src=gBb + (size_t)jt*128*W + p*256 + zc*64;
      uint32_t dst=base+16384+p*16384;
#pragma unroll
      for(int m=0;m<4;++m){ int ch=tid+m*256, r=ch>>3, cx=ch&7;
        cp16(dst+swz(r,cx), src+(size_t)r*W+cx*8); }
    }
    cpc();
  };
  loadChunk(0,0,0);

  // colsum(V) from global
  const float* gV = V + (size_t)b*Sn*8;
  {
    int e=tid&7, jg=tid>>3; float part=0.f;
#pragma unroll
    for(int k=0;k<32;++k) part+=gV[(jg+k*32)*8+e];
    *(float*)(smem+SM_CS+(jg*8+e)*4)=part;
  }
  __syncthreads();
  if(tid<8){ float s=0.f; for(int g=0;g<32;++g) s+=*(float*)(smem+SM_CS+(g*8+tid)*4);
             *(float*)(smem+SM_SV+tid*4)=s; }

  uint32_t accX[2][4][2], accY[2][4][2], accZ[2][4][2];  // f16x2 accs
  float accO[2][4];
#pragma unroll
  for(int m=0;m<2;++m)
#pragma unroll
    for(int x=0;x<4;++x){ accO[m][x]=0.f; }

  const int lr=lane&15, lch=lane>>4;
  const int brow=(lane&7)+((lane>>4)<<3), bco=(lane>>3)&1;
  const int ve=lane>>2, vj=2*(lane&3);

  for(int jt=0;jt<8;++jt){
#pragma unroll
    for(int zc=0;zc<4;++zc){            // zc compile-time
      asm volatile("cp.async.wait_group 0;\n":::"memory");
      __syncthreads();
      if(jt<7||zc<3){                    // prefetch next chunk into other stage
        int nj=(zc==3)?jt+1:jt, nz=(zc==3)?0:zc+1;
        loadChunk(nj,nz,(zc+1)&1);
      }
      uint32_t vf[2][2];
      if(zc==3){                         // hoist V frag LDGs over the last chunk
#pragma unroll
        for(int q=0;q<2;++q){
          int j0=jt*128+wn*32+q*16+vj;
          float v0=gV[j0*8+ve],     v1=gV[(j0+1)*8+ve];
          float v2=gV[(j0+8)*8+ve], v3=gV[(j0+9)*8+ve];
          vf[q][0]=pack2(v0,v1); vf[q][1]=pack2(v2,v3);
        }
      }
      const uint32_t base=sb+SM_RING+(uint32_t)((zc&1)*STG);

#pragma unroll
      for(int k16=0;k16<4;++k16){
        uint32_t aC[2][4], aS[2][4], bC[2][4], bS[2][4];
#pragma unroll
        for(int m=0;m<2;++m){
          ldsm_x4(aC[m], base+        swz(wm*32+m*16+lr, k16*2+lch));
          ldsm_x4(aS[m], base+8192 +  swz(wm*32+m*16+lr, k16*2+lch));
        }
#pragma unroll
        for(int h=0;h<2;++h){
          ldsm_x4(bC[h], base+16384 + swz(wn*32+h*16+brow, k16*2+bco));
          ldsm_x4(bS[h], base+32768 + swz(wn*32+h*16+brow, k16*2+bco));
        }
        // pass 1: X += aC*bC  (m1) -- aC dies into d after this
#pragma unroll
        for(int m=0;m<2;++m)
#pragma unroll
          for(int nf=0;nf<4;++nf){
            uint32_t b0=bC[nf>>1][(nf&1)*2], b1=bC[nf>>1][(nf&1)*2+1];
            if(zc==0&&k16==0) mma16816h_z(accX[m][nf], aC[m], b0, b1);
            else              mma16816h  (accX[m][nf], aC[m], b0, b1);
          }
        // d = aC - aS (overwrite aC)
#pragma unroll
        for(int m=0;m<2;++m)
#pragma unroll
          for(int i=0;i<4;++i) aC[m][i]=hsub2(aC[m][i],aS[m][i]);
        // pass 2: Y += aS*bS  (m2)
#pragma unroll
        for(int m=0;m<2;++m)
#pragma unroll
          for(int nf=0;nf<4;++nf){
            uint32_t b0=bS[nf>>1][(nf&1)*2], b1=bS[nf>>1][(nf&1)*2+1];
            if(zc==0&&k16==0) mma16816h_z(accY[m][nf], aS[m], b0, b1);
            else              mma16816h  (accY[m][nf], aS[m], b0, b1);
          }
        // e = bC + bS (overwrite bC)
#pragma unroll
        for(int h=0;h<2;++h)
#pragma unroll
          for(int i=0;i<4;++i) bC[h][i]=hadd2(bC[h][i],bS[h][i]);
        // pass 3: Z += d*e  (m3)
#pragma unroll
        for(int m=0;m<2;++m)
#pragma unroll
          for(int nf=0;nf<4;++nf){
            uint32_t b0=bC[nf>>1][(nf&1)*2], b1=bC[nf>>1][(nf&1)*2+1];
            if(zc==0&&k16==0) mma16816h_z(accZ[m][nf], aC[m], b0, b1);
            else              mma16816h  (accZ[m][nf], aC[m], b0, b1);
          }
      }

      if(zc==3){   // u=X+Y (re/256), v=Z-X+Y (im/256); P = 2(u^2+v^2) all f16x2
#pragma unroll
        for(int m=0;m<2;++m)
#pragma unroll
          for(int q=0;q<2;++q){
            const int n0=2*q, n1=2*q+1;
            uint32_t pa[4];
#pragma unroll
            for(int r2=0;r2<2;++r2){
              uint32_t u0=hadd2(accX[m][n0][r2],accY[m][n0][r2]);
              uint32_t v0=hsub2(hadd2(accZ[m][n0][r2],accY[m][n0][r2]),accX[m][n0][r2]);
              uint32_t p0=hfma2(v0,v0,hmul2(u0,u0));
              pa[r2]=hadd2(p0,p0);
              uint32_t u1=hadd2(accX[m][n1][r2],accY[m][n1][r2]);
              uint32_t v1=hsub2(hadd2(accZ[m][n1][r2],accY[m][n1][r2]),accX[m][n1][r2]);
              uint32_t p1=hfma2(v1,v1,hmul2(u1,u1));
              pa[2+r2]=hadd2(p1,p1);
            }
            mma16816(accO[m], pa, vf[q][0], vf[q][1]);
          }
        // no re-zeroing: next jt's first mma uses the zero-C forms
      }
    }
  }

  __syncthreads();
  // reduce 4 warpN partials, subtract colsum(V), store (64 rows x 8)
  {
    float* red=(float*)(smem+SM_RED)+wn*512;
    const int g=lane>>2, e0=(lane&3)*2;
#pragma unroll
    for(int m=0;m<2;++m){
      int r0=wm*32+m*16+g;
      red[r0*8+e0]=accO[m][0];     red[r0*8+e0+1]=accO[m][1];
      red[(r0+8)*8+e0]=accO[m][2]; red[(r0+8)*8+e0+1]=accO[m][3];
    }
  }
  __syncthreads();
  const float* redall=(const float*)(smem+SM_RED);
  size_t ob=(size_t)(b*Sn+it*64)*8;
#pragma unroll
  for(int rep=0;rep<2;++rep){
    int idx=tid+rep*256, e=idx&7;
    float v=redall[idx]+redall[512+idx]+redall[1024+idx]+redall[1536+idx]
           -*(const float*)(smem+SM_SV+e*4);
    Out[ob+idx]=v;
  }
}

extern "C" void kernel_launch(void* const* d_in,const int* in_sizes,int n_in,void* d_out,int out_size){
  (void)in_sizes;(void)n_in;(void)out_size;
  const float* Q=(const float*)d_in[0];
  const float* K=(const float*)d_in[1];
  const float* V=(const float*)d_in[2];
  float* Out=(float*)d_out;
  dim3 g1(Bn*Sn/16,2);
  iqp_amp_kernel<<<g1,256>>>(Q,K);
  cudaFuncSetAttribute(qattn_kernel,cudaFuncAttributeMaxDynamicSharedMemorySize,SM_TOTAL);
  dim3 g2(16,Bn);
  qattn_kernel<<<g2,256,SM_TOTAL>>>(V,Out);
}